// round 7
// baseline (speedup 1.0000x reference)
#include <cuda_runtime.h>
#include <cstdint>

#define GD 256
#define GH 256
#define GW 256
#define NT 16          // tiles per axis
#define TS 16          // tile edge
#define RWIN 6
#define DHW_I 16777216
#define NTILES 4096    // 16^3
#define CAP 512        // max pairs per tile bucket (lambda ~21, safe)

// zero-initialized at module load; splat_tiles self-resets cursors each run
__device__ int   g_cursors[NTILES];
__device__ uint2 g_pairs  [NTILES * CAP];   // 16 MB static scratch

// ---------------------------------------------------------------------------
// Global clipped bounds: bbox [floor(c-r), ceil(c+r)] ∩ [base±RWIN] ∩ grid.
// Exactly matches the reference's in_bbox & in_grid masks (bounds integer-
// valued so int conversion is exact).
// ---------------------------------------------------------------------------
__device__ __forceinline__ bool gbounds(float cx, float cy, float cz, float r,
                                        int& x0, int& x1, int& y0, int& y1,
                                        int& z0, int& z1)
{
    const int bx = (int)floorf(cx);
    const int by = (int)floorf(cy);
    const int bz = (int)floorf(cz);
    x0 = max((int)floorf(cx - r), max(bx - RWIN, 0));
    x1 = min((int)ceilf (cx + r), min(bx + RWIN, GD - 1));
    y0 = max((int)floorf(cy - r), max(by - RWIN, 0));
    y1 = min((int)ceilf (cy + r), min(by + RWIN, GH - 1));
    z0 = max((int)floorf(cz - r), max(bz - RWIN, 0));
    z1 = min((int)ceilf (cz + r), min(bz + RWIN, GW - 1));
    return (x0 <= x1) && (y0 <= y1) && (z0 <= z1);
}

// ---------------------------------------------------------------------------
// Binning: one thread per Gaussian, append (gid, packed tile-local bounds)
// into per-tile fixed-capacity buckets.
// ---------------------------------------------------------------------------
__global__ __launch_bounds__(64)
void scatter_kernel(const float* __restrict__ center,
                    const float* __restrict__ radius, int N)
{
    int g = blockIdx.x * blockDim.x + threadIdx.x;
    if (g >= N) return;
    int x0, x1, y0, y1, z0, z1;
    if (!gbounds(center[3*g], center[3*g+1], center[3*g+2], radius[g],
                 x0, x1, y0, y1, z0, z1)) return;

    for (int tx = x0 >> 4; tx <= (x1 >> 4); ++tx) {
        const int xb = tx * TS;
        const unsigned lx0 = (unsigned)max(x0 - xb, 0);
        const unsigned lx1 = (unsigned)min(x1 - xb, TS - 1);
        for (int ty = y0 >> 4; ty <= (y1 >> 4); ++ty) {
            const int yb = ty * TS;
            const unsigned ly0 = (unsigned)max(y0 - yb, 0);
            const unsigned ly1 = (unsigned)min(y1 - yb, TS - 1);
            for (int tz = z0 >> 4; tz <= (z1 >> 4); ++tz) {
                const int zb = tz * TS;
                const unsigned lz0 = (unsigned)max(z0 - zb, 0);
                const unsigned lz1 = (unsigned)min(z1 - zb, TS - 1);
                const unsigned bb = lx0 | (lx1 << 4) | (ly0 << 8) |
                                    (ly1 << 12) | (lz0 << 16) | (lz1 << 20);
                const int tile = (tx * NT + ty) * NT + tz;
                const int slot = atomicAdd(&g_cursors[tile], 1);
                if (slot < CAP)
                    g_pairs[tile * CAP + slot] = make_uint2((unsigned)g, bb);
            }
        }
    }
}

// ---------------------------------------------------------------------------
// One CTA per 16^3 tile. Thread (lx,ly) owns the z-column; accumulation in
// shared memory (k-major: sAcc[vol][z][col]) -> zero atomics.
//  * inner z-loop is BRANCHLESS: masked voxels get L = -1000 via FSEL and
//    ex2.approx.ftz(-1000) == +0.0f, so they accumulate exactly nothing.
//    (avoids per-iteration BSSY/BSYNC reconvergence overhead)
//  * exponent in log2 domain, forward-differenced along z
//  * tile streamed out once with coalesced float4 stores
//  * resets its own g_cursors[b] for the next graph replay
// ---------------------------------------------------------------------------
__global__ __launch_bounds__(256)
void splat_tiles_kernel(const float* __restrict__ center,
                        const float* __restrict__ covinv,
                        const float* __restrict__ dens_r,
                        const float* __restrict__ dens_i,
                        const float* __restrict__ half_shape,
                        float* __restrict__ out)
{
    const int b  = blockIdx.x;
    const int tz = b & 15, ty = (b >> 4) & 15, tx = b >> 8;
    const int xb = tx * TS, yb = ty * TS, zb = tz * TS;

    const int tid = threadIdx.x;
    const int lx  = tid >> 4;
    const int ly  = tid & 15;

    __shared__ float    sAcc[2][TS][256];   // 32 KB accumulators
    __shared__ float    sp[11][128];        // staged params
    __shared__ unsigned sbnd[128];          // staged packed bounds
    __shared__ int      scnt;

    float* sA = &sAcc[0][0][0];
    #pragma unroll
    for (int i = tid; i < 2 * TS * 256; i += 256) sA[i] = 0.0f;

    if (tid == 0) {
        scnt = min(g_cursors[b], CAP);
        g_cursors[b] = 0;                  // self-reset for next replay
    }
    __syncthreads();

    const float ihx = 1.0f / half_shape[0];
    const float ihy = 1.0f / half_shape[1];
    const float e   = 1.0f / half_shape[2];

    const int cnt = scnt;
    const uint2* __restrict__ bucket = g_pairs + b * CAP;

    const float fvx = (float)(xb + lx);
    const float fvy = (float)(yb + ly);
    const int   wlx = (tid >> 5) * 2;       // warp's x-row pair {wlx, wlx+1}

    const float h   = -0.72134752044448170f;   // -0.5 * log2(e)
    const float Lth = -6.49212768400033530f;   // 9 * h (Md<=9 <=> L>=Lth)

    for (int base = 0; base < cnt; base += 128) {
        const int n = min(cnt - base, 128);
        __syncthreads();
        if (tid < n) {
            const uint2 pr = bucket[base + tid];
            const int g = (int)pr.x;
            sp[0][tid] = center[3*g+0];
            sp[1][tid] = center[3*g+1];
            sp[2][tid] = center[3*g+2];
            sp[3][tid] = covinv[9*g+0];                  // C00
            sp[4][tid] = covinv[9*g+4];                  // C11
            sp[5][tid] = covinv[9*g+8];                  // C22
            sp[6][tid] = covinv[9*g+1] + covinv[9*g+3];  // S01
            sp[7][tid] = covinv[9*g+2] + covinv[9*g+6];  // S02
            sp[8][tid] = covinv[9*g+5] + covinv[9*g+7];  // S12
            sp[9][tid]  = dens_r[g];
            sp[10][tid] = dens_i[g];
            sbnd[tid] = pr.y;
        }
        __syncthreads();

        for (int i = 0; i < n; ++i) {
            const unsigned bbp = sbnd[i];
            const int lx0 = bbp & 15, lx1 = (bbp >> 4) & 15;
            if (lx1 < wlx || lx0 > wlx + 1) continue;   // warp-uniform skip

            const int ly0 = (bbp >> 8) & 15,  ly1 = (bbp >> 12) & 15;
            const int lz0 = (bbp >> 16) & 15, lz1 = (bbp >> 20) & 15;

            const bool xyok = (lx >= lx0) & (lx <= lx1) &
                              (ly >= ly0) & (ly <= ly1);
            if (xyok) {
                const float cx = sp[0][i], cy = sp[1][i], cz = sp[2][i];
                const float dx = (fvx - cx) * ihx;
                const float dy = (fvy - cy) * ihy;

                const float C00 = sp[3][i], C11 = sp[4][i], C22 = sp[5][i];
                const float S01 = sp[6][i], S02 = sp[7][i], S12 = sp[8][i];
                const float wr  = sp[9][i], wi  = sp[10][i];

                const float Bxy = fmaf(S02, dx, S12 * dy);
                const float Cxy = fmaf(fmaf(C00, dx, S01 * dy), dx,
                                       C11 * dy * dy);

                const float dzb = ((float)(zb + lz0) - cz) * e;  // anchor
                const float A   = C22 * e * e;
                const float B   = e * fmaf(2.0f * C22, dzb, Bxy);
                const float C   = fmaf(C22, dzb * dzb, fmaf(Bxy, dzb, Cxy));

                float L   = h * C;            // log2(w) at k = 0
                float dL  = h * (A + B);      // first forward difference
                const float ddL = 2.0f * h * A;

                const int m = lz1 - lz0;
                int z = lz0;
                #pragma unroll 4
                for (int k = 0; k <= m; ++k, ++z) {
                    // branchless mask: ex2.ftz(-1000) == +0.0f
                    const float Ls = (L >= Lth) ? L : -1000.0f;
                    float w;
                    asm("ex2.approx.ftz.f32 %0, %1;" : "=f"(w) : "f"(Ls));
                    sAcc[0][z][tid] = fmaf(w, wr, sAcc[0][z][tid]);
                    sAcc[1][z][tid] = fmaf(w, wi, sAcc[1][z][tid]);
                    L += dL;
                    dL += ddL;
                }
            }
        }
    }

    __syncthreads();

    // writeout: coalesced float4 stores (lanes -> contiguous 512B segments)
    #pragma unroll
    for (int vol = 0; vol < 2; ++vol) {
        float* o = out + (vol ? DHW_I : 0);
        #pragma unroll
        for (int j = 0; j < 4; ++j) {
            const int qi  = tid + 256 * j;
            const int col = qi >> 2;
            const int k0  = (qi & 3) * 4;
            float4 v;
            v.x = sAcc[vol][k0 + 0][col];
            v.y = sAcc[vol][k0 + 1][col];
            v.z = sAcc[vol][k0 + 2][col];
            v.w = sAcc[vol][k0 + 3][col];
            const int gx = xb + (col >> 4);
            const int gy = yb + (col & 15);
            *(float4*)(o + ((gx * GH + gy) * GW + zb + k0)) = v;
        }
    }
}

// ---------------------------------------------------------------------------
extern "C" void kernel_launch(void* const* d_in, const int* in_sizes, int n_in,
                              void* d_out, int out_size) {
    const float* center     = (const float*)d_in[0];  // [N,3]
    const float* covinv     = (const float*)d_in[1];  // [N,3,3]
    const float* dens_r     = (const float*)d_in[2];  // [N]
    const float* dens_i     = (const float*)d_in[3];  // [N]
    const float* radius     = (const float*)d_in[4];  // [N]
    const float* half_shape = (const float*)d_in[5];  // [3]

    float* out = (float*)d_out;                       // [2, D, H, W]
    const int N = in_sizes[2];

    scatter_kernel<<<(N + 63) / 64, 64>>>(center, radius, N);
    splat_tiles_kernel<<<NTILES, 256>>>(center, covinv, dens_r, dens_i,
                                        half_shape, out);
}

// round 8
// speedup vs baseline: 1.0851x; 1.0851x over previous
#include <cuda_runtime.h>
#include <cstdint>

#define GD 256
#define GH 256
#define GW 256
#define NT 16          // tiles per axis
#define TS 16          // tile edge
#define RWIN 6
#define DHW_I 16777216
#define NTILES 4096    // 16^3
#define CAP 512        // max pairs per tile bucket (lambda ~21, safe)

// zero-initialized at module load; splat_tiles self-resets cursors each run
__device__ int   g_cursors[NTILES];
__device__ uint2 g_pairs  [NTILES * CAP];   // 16 MB static scratch

// ---------------------------------------------------------------------------
// Global clipped bounds: bbox [floor(c-r), ceil(c+r)] ∩ [base±RWIN] ∩ grid.
// Exactly matches the reference's in_bbox & in_grid masks (bounds integer-
// valued so int conversion is exact).
// ---------------------------------------------------------------------------
__device__ __forceinline__ bool gbounds(float cx, float cy, float cz, float r,
                                        int& x0, int& x1, int& y0, int& y1,
                                        int& z0, int& z1)
{
    const int bx = (int)floorf(cx);
    const int by = (int)floorf(cy);
    const int bz = (int)floorf(cz);
    x0 = max((int)floorf(cx - r), max(bx - RWIN, 0));
    x1 = min((int)ceilf (cx + r), min(bx + RWIN, GD - 1));
    y0 = max((int)floorf(cy - r), max(by - RWIN, 0));
    y1 = min((int)ceilf (cy + r), min(by + RWIN, GH - 1));
    z0 = max((int)floorf(cz - r), max(bz - RWIN, 0));
    z1 = min((int)ceilf (cz + r), min(bz + RWIN, GW - 1));
    return (x0 <= x1) && (y0 <= y1) && (z0 <= z1);
}

// ---------------------------------------------------------------------------
// Binning: one thread per Gaussian, append (gid, packed tile-local bounds)
// into per-tile fixed-capacity buckets.
// ---------------------------------------------------------------------------
__global__ __launch_bounds__(64)
void scatter_kernel(const float* __restrict__ center,
                    const float* __restrict__ radius, int N)
{
    int g = blockIdx.x * blockDim.x + threadIdx.x;
    if (g >= N) return;
    int x0, x1, y0, y1, z0, z1;
    if (!gbounds(center[3*g], center[3*g+1], center[3*g+2], radius[g],
                 x0, x1, y0, y1, z0, z1)) return;

    for (int tx = x0 >> 4; tx <= (x1 >> 4); ++tx) {
        const int xb = tx * TS;
        const unsigned lx0 = (unsigned)max(x0 - xb, 0);
        const unsigned lx1 = (unsigned)min(x1 - xb, TS - 1);
        for (int ty = y0 >> 4; ty <= (y1 >> 4); ++ty) {
            const int yb = ty * TS;
            const unsigned ly0 = (unsigned)max(y0 - yb, 0);
            const unsigned ly1 = (unsigned)min(y1 - yb, TS - 1);
            for (int tz = z0 >> 4; tz <= (z1 >> 4); ++tz) {
                const int zb = tz * TS;
                const unsigned lz0 = (unsigned)max(z0 - zb, 0);
                const unsigned lz1 = (unsigned)min(z1 - zb, TS - 1);
                const unsigned bb = lx0 | (lx1 << 4) | (ly0 << 8) |
                                    (ly1 << 12) | (lz0 << 16) | (lz1 << 20);
                const int tile = (tx * NT + ty) * NT + tz;
                const int slot = atomicAdd(&g_cursors[tile], 1);
                if (slot < CAP)
                    g_pairs[tile * CAP + slot] = make_uint2((unsigned)g, bb);
            }
        }
    }
}

// ---------------------------------------------------------------------------
// One CTA per 16^3 tile.
//  * warp = 4x * 8y window (better bbox coverage than 2x16: engaged warp
//    visits ~x0.62, lane efficiency ~66%)
//  * accumulators in smem as float2 (r,i): 1 LDS.64 + 1 STS.64 per z
//    (halves LSU instruction rate -- R7's top pipe at 64%)
//  * col = wid*32 + lane: each warp owns 32 CONSECUTIVE float2 cells ->
//    conflict-free 64-bit shared accesses
//  * dynamic z loop over [lz0,lz1] only; log2-domain forward-difference,
//    FSEL mask (Md<=9 <=> L>=Lth), ex2.approx per valid-range voxel
//  * tile streamed out once with coalesced float4 stores
//  * resets its own g_cursors[b] for the next graph replay
// ---------------------------------------------------------------------------
__global__ __launch_bounds__(256)
void splat_tiles_kernel(const float* __restrict__ center,
                        const float* __restrict__ covinv,
                        const float* __restrict__ dens_r,
                        const float* __restrict__ dens_i,
                        const float* __restrict__ half_shape,
                        float* __restrict__ out)
{
    const int b  = blockIdx.x;
    const int tz = b & 15, ty = (b >> 4) & 15, tx = b >> 8;
    const int xb = tx * TS, yb = ty * TS, zb = tz * TS;

    const int tid  = threadIdx.x;
    const int wid  = tid >> 5;
    const int lane = tid & 31;
    const int wx   = (wid & 3) * 4;          // warp window x base (4 wide)
    const int wy   = (wid >> 2) * 8;         // warp window y base (8 tall)
    const int lx   = wx + (lane >> 3);
    const int ly   = wy + (lane & 7);
    const int col  = wid * 32 + lane;        // consecutive per warp

    __shared__ float2   sAcc[TS][256];       // 32 KB (r,i) accumulators
    __shared__ float    sp[11][128];         // staged params
    __shared__ unsigned sbnd[128];           // staged packed bounds
    __shared__ int      scnt;

    #pragma unroll
    for (int i = tid; i < TS * 256; i += 256)
        sAcc[i >> 8][i & 255] = make_float2(0.f, 0.f);

    if (tid == 0) {
        scnt = min(g_cursors[b], CAP);
        g_cursors[b] = 0;                    // self-reset for next replay
    }
    __syncthreads();

    const float ihx = 1.0f / half_shape[0];
    const float ihy = 1.0f / half_shape[1];
    const float e   = 1.0f / half_shape[2];

    const int cnt = scnt;
    const uint2* __restrict__ bucket = g_pairs + b * CAP;

    const float fvx = (float)(xb + lx);
    const float fvy = (float)(yb + ly);

    const float h   = -0.72134752044448170f;   // -0.5 * log2(e)
    const float Lth = -6.49212768400033530f;   // 9 * h (Md<=9 <=> L>=Lth)

    for (int base = 0; base < cnt; base += 128) {
        const int n = min(cnt - base, 128);
        __syncthreads();
        if (tid < n) {
            const uint2 pr = bucket[base + tid];
            const int g = (int)pr.x;
            sp[0][tid] = center[3*g+0];
            sp[1][tid] = center[3*g+1];
            sp[2][tid] = center[3*g+2];
            sp[3][tid] = covinv[9*g+0];                  // C00
            sp[4][tid] = covinv[9*g+4];                  // C11
            sp[5][tid] = covinv[9*g+8];                  // C22
            sp[6][tid] = covinv[9*g+1] + covinv[9*g+3];  // S01
            sp[7][tid] = covinv[9*g+2] + covinv[9*g+6];  // S02
            sp[8][tid] = covinv[9*g+5] + covinv[9*g+7];  // S12
            sp[9][tid]  = dens_r[g];
            sp[10][tid] = dens_i[g];
            sbnd[tid] = pr.y;
        }
        __syncthreads();

        for (int i = 0; i < n; ++i) {
            const unsigned bbp = sbnd[i];
            const int lx0 = bbp & 15, lx1 = (bbp >> 4) & 15;
            const int ly0 = (bbp >> 8) & 15,  ly1 = (bbp >> 12) & 15;
            // warp-uniform window overlap test (both dims)
            if (lx1 < wx || lx0 > wx + 3 || ly1 < wy || ly0 > wy + 7)
                continue;

            const int lz0 = (bbp >> 16) & 15, lz1 = (bbp >> 20) & 15;

            const bool xyok = (lx >= lx0) & (lx <= lx1) &
                              (ly >= ly0) & (ly <= ly1);
            if (xyok) {
                const float cx = sp[0][i], cy = sp[1][i], cz = sp[2][i];
                const float dx = (fvx - cx) * ihx;
                const float dy = (fvy - cy) * ihy;

                const float C00 = sp[3][i], C11 = sp[4][i], C22 = sp[5][i];
                const float S01 = sp[6][i], S02 = sp[7][i], S12 = sp[8][i];
                const float wr  = sp[9][i], wi  = sp[10][i];

                const float Bxy = fmaf(S02, dx, S12 * dy);
                const float Cxy = fmaf(fmaf(C00, dx, S01 * dy), dx,
                                       C11 * dy * dy);

                const float dzb = ((float)(zb + lz0) - cz) * e;  // anchor
                const float A   = C22 * e * e;
                const float B   = e * fmaf(2.0f * C22, dzb, Bxy);
                const float C   = fmaf(C22, dzb * dzb, fmaf(Bxy, dzb, Cxy));

                float L   = h * C;            // log2(w) at k = 0
                float dL  = h * (A + B);      // first forward difference
                const float ddL = 2.0f * h * A;

                float2* ap = &sAcc[lz0][col];
                const int m = lz1 - lz0;
                #pragma unroll 4
                for (int k = 0; k <= m; ++k) {
                    const float Ls = (L >= Lth) ? L : -1000.0f;
                    float w;
                    asm("ex2.approx.ftz.f32 %0, %1;" : "=f"(w) : "f"(Ls));
                    float2 v = *ap;
                    v.x = fmaf(w, wr, v.x);
                    v.y = fmaf(w, wi, v.y);
                    *ap = v;
                    ap += 256;
                    L += dL;
                    dL += ddL;
                }
            }
        }
    }

    __syncthreads();

    // writeout: thread qi handles 4 z of one column; 4 consecutive lanes
    // cover 64B contiguous gmem -> clean sector-aligned float4 stores.
    #pragma unroll
    for (int j = 0; j < 4; ++j) {
        const int qi = tid + 256 * j;
        const int c  = qi >> 2;
        const int k0 = (qi & 3) * 4;
        // invert col mapping: c -> (lx, ly)
        const int cw = c >> 5, cl = c & 31;
        const int gx = xb + (cw & 3) * 4 + (cl >> 3);
        const int gy = yb + (cw >> 2) * 8 + (cl & 7);

        const float2 a0 = sAcc[k0 + 0][c];
        const float2 a1 = sAcc[k0 + 1][c];
        const float2 a2 = sAcc[k0 + 2][c];
        const float2 a3 = sAcc[k0 + 3][c];

        const int idx = (gx * GH + gy) * GW + zb + k0;
        *(float4*)(out + idx)         = make_float4(a0.x, a1.x, a2.x, a3.x);
        *(float4*)(out + idx + DHW_I) = make_float4(a0.y, a1.y, a2.y, a3.y);
    }
}

// ---------------------------------------------------------------------------
extern "C" void kernel_launch(void* const* d_in, const int* in_sizes, int n_in,
                              void* d_out, int out_size) {
    const float* center     = (const float*)d_in[0];  // [N,3]
    const float* covinv     = (const float*)d_in[1];  // [N,3,3]
    const float* dens_r     = (const float*)d_in[2];  // [N]
    const float* dens_i     = (const float*)d_in[3];  // [N]
    const float* radius     = (const float*)d_in[4];  // [N]
    const float* half_shape = (const float*)d_in[5];  // [3]

    float* out = (float*)d_out;                       // [2, D, H, W]
    const int N = in_sizes[2];

    scatter_kernel<<<(N + 63) / 64, 64>>>(center, radius, N);
    splat_tiles_kernel<<<NTILES, 256>>>(center, covinv, dens_r, dens_i,
                                        half_shape, out);
}

// round 9
// speedup vs baseline: 1.1477x; 1.0576x over previous
#include <cuda_runtime.h>
#include <cstdint>

#define GD 256
#define GH 256
#define GW 256
#define NT 16
#define TS 16
#define RWIN 6
#define DHW_I 16777216
#define NTILES 4096
#define CAP 512
#define MAXN 32768
#define CHUNK 64

// zero-initialized at module load; splat_tiles self-resets cursors each run
__device__ int    g_cursors[NTILES];
__device__ uint2  g_pairs  [NTILES * CAP];
__device__ float4 g_params [MAXN * 3];     // {cx,cy,cz,C00},{C11,C22,S01,S02},{S12,wr,wi,-}

// ---------------------------------------------------------------------------
__device__ __forceinline__ bool gbounds(float cx, float cy, float cz, float r,
                                        int& x0, int& x1, int& y0, int& y1,
                                        int& z0, int& z1)
{
    const int bx = (int)floorf(cx);
    const int by = (int)floorf(cy);
    const int bz = (int)floorf(cz);
    x0 = max((int)floorf(cx - r), max(bx - RWIN, 0));
    x1 = min((int)ceilf (cx + r), min(bx + RWIN, GD - 1));
    y0 = max((int)floorf(cy - r), max(by - RWIN, 0));
    y1 = min((int)ceilf (cy + r), min(by + RWIN, GH - 1));
    z0 = max((int)floorf(cz - r), max(bz - RWIN, 0));
    z1 = min((int)ceilf (cz + r), min(bz + RWIN, GW - 1));
    return (x0 <= x1) && (y0 <= y1) && (z0 <= z1);
}

// ---------------------------------------------------------------------------
// Binning + per-Gaussian param packing. Pair record: (gid, packed bounds +
// 8-bit warp-window mask). Warp windows in splat are 4x(x) * 8y(y), wid =
// xwin + 4*ywin ... (wid&3)=xwin, (wid>>2)=ywin.
// ---------------------------------------------------------------------------
__global__ __launch_bounds__(64)
void scatter_kernel(const float* __restrict__ center,
                    const float* __restrict__ covinv,
                    const float* __restrict__ dens_r,
                    const float* __restrict__ dens_i,
                    const float* __restrict__ radius, int N)
{
    int g = blockIdx.x * blockDim.x + threadIdx.x;
    if (g >= N) return;

    const float cx = center[3*g+0], cy = center[3*g+1], cz = center[3*g+2];

    // pack params (S terms pre-folded)
    g_params[3*g+0] = make_float4(cx, cy, cz, covinv[9*g+0]);
    g_params[3*g+1] = make_float4(covinv[9*g+4], covinv[9*g+8],
                                  covinv[9*g+1] + covinv[9*g+3],
                                  covinv[9*g+2] + covinv[9*g+6]);
    g_params[3*g+2] = make_float4(covinv[9*g+5] + covinv[9*g+7],
                                  dens_r[g], dens_i[g], 0.0f);

    int x0, x1, y0, y1, z0, z1;
    if (!gbounds(cx, cy, cz, radius[g], x0, x1, y0, y1, z0, z1)) return;

    for (int tx = x0 >> 4; tx <= (x1 >> 4); ++tx) {
        const int xb = tx * TS;
        const unsigned lx0 = (unsigned)max(x0 - xb, 0);
        const unsigned lx1 = (unsigned)min(x1 - xb, TS - 1);
        // x-window mask (windows of width 4)
        unsigned xm = 0;
        #pragma unroll
        for (int w = 0; w < 4; ++w)
            if (lx0 <= (unsigned)(4*w + 3) && lx1 >= (unsigned)(4*w)) xm |= 1u << w;
        for (int ty = y0 >> 4; ty <= (y1 >> 4); ++ty) {
            const int yb = ty * TS;
            const unsigned ly0 = (unsigned)max(y0 - yb, 0);
            const unsigned ly1 = (unsigned)min(y1 - yb, TS - 1);
            unsigned m8 = 0;
            if (ly0 <= 7u)               m8 |= xm;        // ywin 0
            if (ly1 >= 8u)               m8 |= xm << 4;   // ywin 1
            for (int tz = z0 >> 4; tz <= (z1 >> 4); ++tz) {
                const int zb = tz * TS;
                const unsigned lz0 = (unsigned)max(z0 - zb, 0);
                const unsigned lz1 = (unsigned)min(z1 - zb, TS - 1);
                const unsigned bb = lx0 | (lx1 << 4) | (ly0 << 8) |
                                    (ly1 << 12) | (lz0 << 16) | (lz1 << 20) |
                                    (m8 << 24);
                const int tile = (tx * NT + ty) * NT + tz;
                const int slot = atomicAdd(&g_cursors[tile], 1);
                if (slot < CAP)
                    g_pairs[tile * CAP + slot] = make_uint2((unsigned)g, bb);
            }
        }
    }
}

// ---------------------------------------------------------------------------
// One CTA per 16^3 tile.
//  * warp = 4x * 8y window; 8-bit pair mask -> ~3-instr skip for idle warps
//  * accumulators: sAccP[zp][col] float4 {r(2zp),i(2zp),r(2zp+1),i(2zp+1)};
//    col = wid*32+lane -> warp accesses 512B CONTIGUOUS -> LDS/STS.128,
//    2 voxels per instruction pair, conflict-free
//  * two interleaved log2-domain forward-difference chains (even/odd z),
//    even anchor z0e = lz0&~1; mask via FSEL, ex2.ftz(-1000) == +0.0f
//  * params staged as 3 x float4 per pair (LDS.128 broadcasts)
//  * tile streamed out once; resets its own cursor for the next replay
// ---------------------------------------------------------------------------
__global__ __launch_bounds__(256)
void splat_tiles_kernel(const float* __restrict__ half_shape,
                        float* __restrict__ out)
{
    const int b  = blockIdx.x;
    const int tz = b & 15, ty = (b >> 4) & 15, tx = b >> 8;
    const int xb = tx * TS, yb = ty * TS, zb = tz * TS;

    const int tid  = threadIdx.x;
    const int wid  = tid >> 5;
    const int lane = tid & 31;
    const int wx   = (wid & 3) * 4;
    const int wy   = (wid >> 2) * 8;
    const int lx   = wx + (lane >> 3);
    const int ly   = wy + (lane & 7);
    const int col  = wid * 32 + lane;
    const unsigned wbit = 1u << wid;

    __shared__ float4   sAccP[8][256];     // 32 KB z-paired accumulators
    __shared__ float4   sp4[CHUNK * 3];    // staged params
    __shared__ unsigned sbnd[CHUNK];
    __shared__ int      scnt;

    #pragma unroll
    for (int i = tid; i < 8 * 256; i += 256)
        sAccP[i >> 8][i & 255] = make_float4(0.f, 0.f, 0.f, 0.f);

    if (tid == 0) {
        scnt = min(g_cursors[b], CAP);
        g_cursors[b] = 0;                  // self-reset for next replay
    }
    __syncthreads();

    const float ihx = 1.0f / half_shape[0];
    const float ihy = 1.0f / half_shape[1];
    const float e   = 1.0f / half_shape[2];

    const int cnt = scnt;
    const uint2* __restrict__ bucket = g_pairs + b * CAP;

    const float fvx = (float)(xb + lx);
    const float fvy = (float)(yb + ly);

    const float h   = -0.72134752044448170f;   // -0.5 * log2(e)
    const float Lth = -6.49212768400033530f;   // 9 * h (Md<=9 <=> L>=Lth)

    for (int base = 0; base < cnt; base += CHUNK) {
        const int n = min(cnt - base, CHUNK);
        __syncthreads();
        if (tid < n) {
            const uint2 pr = bucket[base + tid];
            const int g = (int)pr.x;
            sp4[3*tid+0] = g_params[3*g+0];
            sp4[3*tid+1] = g_params[3*g+1];
            sp4[3*tid+2] = g_params[3*g+2];
            sbnd[tid] = pr.y;
        }
        __syncthreads();

        for (int i = 0; i < n; ++i) {
            const unsigned bbp = sbnd[i];
            if (!((bbp >> 24) & wbit)) continue;      // cheap warp skip

            const int lx0 = bbp & 15,         lx1 = (bbp >> 4) & 15;
            const int ly0 = (bbp >> 8) & 15,  ly1 = (bbp >> 12) & 15;
            const bool xyok = (lx >= lx0) & (lx <= lx1) &
                              (ly >= ly0) & (ly <= ly1);
            if (xyok) {
                const int lz0 = (bbp >> 16) & 15, lz1 = (bbp >> 20) & 15;

                const float4 p0 = sp4[3*i+0];
                const float4 p1 = sp4[3*i+1];
                const float4 p2 = sp4[3*i+2];
                const float cx = p0.x, cy = p0.y, cz = p0.z, C00 = p0.w;
                const float C11 = p1.x, C22 = p1.y, S01 = p1.z, S02 = p1.w;
                const float S12 = p2.x, wr = p2.y, wi = p2.z;

                const float dx = (fvx - cx) * ihx;
                const float dy = (fvy - cy) * ihy;

                const float Bxy = fmaf(S02, dx, S12 * dy);
                const float Cxy = fmaf(fmaf(C00, dx, S01 * dy), dx,
                                       C11 * dy * dy);

                const int z0e = lz0 & ~1;              // even anchor
                const float dzb = ((float)(zb + z0e) - cz) * e;
                const float A = C22 * e * e;
                const float B = e * fmaf(2.0f * C22, dzb, Bxy);
                const float C = fmaf(C22, dzb * dzb, fmaf(Bxy, dzb, Cxy));

                const float hA = h * A, hB = h * B, hC = h * C;
                float L0  = hC;                         // k = 0
                float L1  = hA + hB + hC;               // k = 1
                float dL0 = 4.0f * hA + 2.0f * hB;      // L(k+2)-L(k), k=0
                float dL1 = 8.0f * hA + 2.0f * hB;      // k=1
                const float dd = 8.0f * hA;

                float4* ap = &sAccP[z0e >> 1][col];
                int zc = z0e;
                const int tmax = (lz1 - z0e) >> 1;
                for (int t = 0; t <= tmax; ++t) {
                    const bool v0 = (zc >= lz0);        // zc<=lz1 always
                    const bool v1 = (zc + 1 <= lz1);
                    const float Ls0 = (v0 && L0 >= Lth) ? L0 : -1000.0f;
                    const float Ls1 = (v1 && L1 >= Lth) ? L1 : -1000.0f;
                    float w0, w1;
                    asm("ex2.approx.ftz.f32 %0, %1;" : "=f"(w0) : "f"(Ls0));
                    asm("ex2.approx.ftz.f32 %0, %1;" : "=f"(w1) : "f"(Ls1));
                    float4 v = *ap;
                    v.x = fmaf(w0, wr, v.x);
                    v.y = fmaf(w0, wi, v.y);
                    v.z = fmaf(w1, wr, v.z);
                    v.w = fmaf(w1, wi, v.w);
                    *ap = v;
                    ap += 256;
                    L0 += dL0; dL0 += dd;
                    L1 += dL1; dL1 += dd;
                    zc += 2;
                }
            }
        }
    }

    __syncthreads();

    // writeout: thread qi=(c,k) writes z quad [4k,4k+3] of column c.
    #pragma unroll
    for (int j = 0; j < 4; ++j) {
        const int qi = tid + 256 * j;
        const int c  = qi >> 2;
        const int k  = qi & 3;
        const float4 a = sAccP[2*k + 0][c];
        const float4 bq = sAccP[2*k + 1][c];
        const int cw = c >> 5, cl = c & 31;
        const int gx = xb + (cw & 3) * 4 + (cl >> 3);
        const int gy = yb + (cw >> 2) * 8 + (cl & 7);
        const int idx = (gx * GH + gy) * GW + zb + 4 * k;
        *(float4*)(out + idx)         = make_float4(a.x, a.z, bq.x, bq.z);
        *(float4*)(out + idx + DHW_I) = make_float4(a.y, a.w, bq.y, bq.w);
    }
}

// ---------------------------------------------------------------------------
extern "C" void kernel_launch(void* const* d_in, const int* in_sizes, int n_in,
                              void* d_out, int out_size) {
    const float* center     = (const float*)d_in[0];
    const float* covinv     = (const float*)d_in[1];
    const float* dens_r     = (const float*)d_in[2];
    const float* dens_i     = (const float*)d_in[3];
    const float* radius     = (const float*)d_in[4];
    const float* half_shape = (const float*)d_in[5];

    float* out = (float*)d_out;
    const int N = in_sizes[2];

    scatter_kernel<<<(N + 63) / 64, 64>>>(center, covinv, dens_r, dens_i,
                                          radius, N);
    splat_tiles_kernel<<<NTILES, 256>>>(half_shape, out);
}